// round 2
// baseline (speedup 1.0000x reference)
#include <cuda_runtime.h>
#include <cstdint>

// Problem constants
#define N_NODES 100000
#define IN_F    256
#define HID     128
#define OUTF    64
#define NNZ_C   1600000
#define EQ_C    200000

// Scratch (device globals — no allocation allowed)
__device__ float g_h0[(size_t)N_NODES * HID];   // x@W1+b1
__device__ float g_h [(size_t)N_NODES * HID];   // relu(spmm(h0))
__device__ float g_z0[(size_t)N_NODES * OUTF];  // h@W2+b2
__device__ float g_z [(size_t)N_NODES * OUTF];  // spmm(z0)
__device__ int   g_rp[N_NODES + 1];             // CSR row pointers

// ---------------------------------------------------------------------------
// Build CSR row_ptr from the sorted rows array.
// ---------------------------------------------------------------------------
__global__ void build_rowptr_kernel(const int* __restrict__ rows, int nnz) {
    int e = blockIdx.x * blockDim.x + threadIdx.x;
    if (e >= nnz) return;
    int r = rows[e];
    int rprev = (e == 0) ? -1 : rows[e - 1];
    for (int rr = rprev + 1; rr <= r; ++rr) g_rp[rr] = e;
    if (e == nnz - 1) {
        for (int rr = r + 1; rr <= N_NODES; ++rr) g_rp[rr] = nnz;
    }
}

// ---------------------------------------------------------------------------
// Tiled fp32 GEMM + bias: C[M,NC] = A[M,K] @ W[K,NC] + b
// BM=64 rows/block, full NC columns. blockDim=256 (16x16), thread tile 4xTN.
// ---------------------------------------------------------------------------
template <int K, int NC, int TN>
__global__ __launch_bounds__(256) void gemm_bias_kernel(
    const float* __restrict__ A, const float* __restrict__ W,
    const float* __restrict__ bias, float* __restrict__ C, int M)
{
    constexpr int BM = 64, BK = 16;
    __shared__ float As[BM][BK];
    __shared__ float Ws[BK][NC];

    const int tid = threadIdx.x;
    const int tx = tid & 15;        // 0..15 -> column group
    const int ty = tid >> 4;        // 0..15 -> row group
    const int r0 = blockIdx.x * BM;

    float acc[4][TN];
#pragma unroll
    for (int i = 0; i < 4; ++i)
#pragma unroll
        for (int j = 0; j < TN; ++j) acc[i][j] = 0.f;

    for (int kt = 0; kt < K; kt += BK) {
        // Load A tile: 64x16 floats = 256 float4, 1 per thread
        {
            int row = tid >> 2;          // 0..63
            int kq  = tid & 3;           // 0..3
            float4 v = make_float4(0.f, 0.f, 0.f, 0.f);
            if (r0 + row < M)
                v = *(const float4*)(A + (size_t)(r0 + row) * K + kt + kq * 4);
            *(float4*)(&As[row][kq * 4]) = v;
        }
        // Load W tile: 16xNC floats
#pragma unroll
        for (int idx = tid; idx < BK * NC / 4; idx += 256) {
            int kr = idx / (NC / 4);
            int cq = idx % (NC / 4);
            *(float4*)(&Ws[kr][cq * 4]) =
                *(const float4*)(W + (size_t)(kt + kr) * NC + cq * 4);
        }
        __syncthreads();

#pragma unroll
        for (int k = 0; k < BK; ++k) {
            float a[4];
#pragma unroll
            for (int i = 0; i < 4; ++i) a[i] = As[ty * 4 + i][k];
            float w[TN];
#pragma unroll
            for (int j = 0; j < TN; ++j) w[j] = Ws[k][tx * TN + j];
#pragma unroll
            for (int i = 0; i < 4; ++i)
#pragma unroll
                for (int j = 0; j < TN; ++j)
                    acc[i][j] = fmaf(a[i], w[j], acc[i][j]);
        }
        __syncthreads();
    }

#pragma unroll
    for (int i = 0; i < 4; ++i) {
        int r = r0 + ty * 4 + i;
        if (r < M) {
#pragma unroll
            for (int j = 0; j < TN; ++j)
                C[(size_t)r * NC + tx * TN + j] = acc[i][j] + bias[tx * TN + j];
        }
    }
}

// ---------------------------------------------------------------------------
// CSR SpMM: out[r,f] = sum_{e in row r} vals[e] * dense[cols[e], f]
// One block per row, one thread per feature. 4-way edge unroll for MLP.
// ---------------------------------------------------------------------------
template <int F, bool RELU>
__global__ void spmm_kernel(const int* __restrict__ cols,
                            const float* __restrict__ vals,
                            const float* __restrict__ dense,
                            float* __restrict__ out)
{
    const int r = blockIdx.x;
    const int f = threadIdx.x;
    const int s = g_rp[r];
    const int e_end = g_rp[r + 1];

    float acc = 0.f;
    int e = s;
    for (; e + 4 <= e_end; e += 4) {
        int c0 = __ldg(cols + e);
        int c1 = __ldg(cols + e + 1);
        int c2 = __ldg(cols + e + 2);
        int c3 = __ldg(cols + e + 3);
        float v0 = __ldg(vals + e);
        float v1 = __ldg(vals + e + 1);
        float v2 = __ldg(vals + e + 2);
        float v3 = __ldg(vals + e + 3);
        float d0 = __ldg(dense + (size_t)c0 * F + f);
        float d1 = __ldg(dense + (size_t)c1 * F + f);
        float d2 = __ldg(dense + (size_t)c2 * F + f);
        float d3 = __ldg(dense + (size_t)c3 * F + f);
        acc = fmaf(v0, d0, acc);
        acc = fmaf(v1, d1, acc);
        acc = fmaf(v2, d2, acc);
        acc = fmaf(v3, d3, acc);
    }
    for (; e < e_end; ++e)
        acc = fmaf(__ldg(vals + e),
                   __ldg(dense + (size_t)__ldg(cols + e) * F + f), acc);

    out[(size_t)r * F + f] = RELU ? fmaxf(acc, 0.f) : acc;
}

// ---------------------------------------------------------------------------
// Decode: out[q] = dot(z[src[q]], z[dst[q]]) over OUTF=64 dims. Warp per edge.
// ---------------------------------------------------------------------------
__global__ void decode_kernel(const int* __restrict__ ei,
                              const float* __restrict__ z,
                              float* __restrict__ out, int eq)
{
    int q = blockIdx.x * 8 + (threadIdx.x >> 5);
    if (q >= eq) return;
    int lane = threadIdx.x & 31;
    int s = __ldg(ei + q);
    int d = __ldg(ei + eq + q);
    const float* zs = z + (size_t)s * OUTF;
    const float* zd = z + (size_t)d * OUTF;
    float p = zs[lane] * zd[lane] + zs[lane + 32] * zd[lane + 32];
#pragma unroll
    for (int o = 16; o > 0; o >>= 1) p += __shfl_down_sync(0xffffffffu, p, o);
    if (lane == 0) out[q] = p;
}

// ---------------------------------------------------------------------------
// Launch
// ---------------------------------------------------------------------------
extern "C" void kernel_launch(void* const* d_in, const int* in_sizes, int n_in,
                              void* d_out, int out_size)
{
    const float* x        = (const float*)d_in[0];   // [N, 256]
    const int*   adj_rows = (const int*)  d_in[1];   // [NNZ] sorted
    const int*   adj_cols = (const int*)  d_in[2];   // [NNZ]
    const float* adj_vals = (const float*)d_in[3];   // [NNZ]
    const int*   edge_idx = (const int*)  d_in[4];   // [2, EQ]
    const float* W1       = (const float*)d_in[5];   // [256, 128]
    const float* b1       = (const float*)d_in[6];   // [128]
    const float* W2       = (const float*)d_in[7];   // [128, 64]
    const float* b2       = (const float*)d_in[8];   // [64]
    float* out = (float*)d_out;                      // [EQ]

    const int nnz = in_sizes[1];
    const int eq  = in_sizes[4] / 2;
    const int M   = N_NODES;

    float* h0 = nullptr; cudaGetSymbolAddress((void**)&h0, g_h0);
    float* h  = nullptr; cudaGetSymbolAddress((void**)&h,  g_h);
    float* z0 = nullptr; cudaGetSymbolAddress((void**)&z0, g_z0);
    float* z  = nullptr; cudaGetSymbolAddress((void**)&z,  g_z);

    // 1. row pointers from sorted rows
    build_rowptr_kernel<<<(nnz + 255) / 256, 256>>>(adj_rows, nnz);

    // 2. h0 = x @ W1 + b1
    gemm_bias_kernel<IN_F, HID, 8><<<(M + 63) / 64, 256>>>(x, W1, b1, h0, M);

    // 3. h = relu(spmm(h0))
    spmm_kernel<HID, true><<<M, HID>>>(adj_cols, adj_vals, h0, h);

    // 4. z0 = h @ W2 + b2
    gemm_bias_kernel<HID, OUTF, 4><<<(M + 63) / 64, 256>>>(h, W2, b2, z0, M);

    // 5. z = spmm(z0)
    spmm_kernel<OUTF, false><<<M, OUTF>>>(adj_cols, adj_vals, z0, z);

    // 6. edge dot products
    decode_kernel<<<(eq + 7) / 8, 256>>>(edge_idx, z, out, eq);
}

// round 4
// speedup vs baseline: 1.3888x; 1.3888x over previous
#include <cuda_runtime.h>
#include <cstdint>

// Problem constants
#define N_NODES 100000
#define IN_F    256
#define HID     128
#define OUTF    64

// Scratch (device globals — no allocation allowed)
__device__ float g_h0[(size_t)N_NODES * HID];   // x@W1+b1
__device__ float g_h [(size_t)N_NODES * HID];   // relu(spmm(h0))
__device__ float g_z0[(size_t)N_NODES * OUTF];  // h@W2+b2
__device__ float g_z [(size_t)N_NODES * OUTF];  // spmm(z0)
__device__ int   g_rp[N_NODES + 1];             // CSR row pointers

// ---------------------------------------------------------------------------
// Build CSR row_ptr from the sorted rows array.
// ---------------------------------------------------------------------------
__global__ void build_rowptr_kernel(const int* __restrict__ rows, int nnz) {
    int e = blockIdx.x * blockDim.x + threadIdx.x;
    if (e >= nnz) return;
    int r = rows[e];
    int rprev = (e == 0) ? -1 : rows[e - 1];
    for (int rr = rprev + 1; rr <= r; ++rr) g_rp[rr] = e;
    if (e == nnz - 1) {
        for (int rr = r + 1; rr <= N_NODES; ++rr) g_rp[rr] = nnz;
    }
}

// ---------------------------------------------------------------------------
// Register-blocked fp32 GEMM + bias: C[M,BNtotal] = A[M,K] @ W[K,BN] + b
// BM=128 rows/block, BN = full output width (one block column).
// Thread tile 8x8; per k-step: 4x LDS.128 -> 64 FMA.
// ---------------------------------------------------------------------------
template <int K, int BN>
__global__ __launch_bounds__(16 * (BN / 8)) void gemm_bias_kernel(
    const float* __restrict__ A, const float* __restrict__ W,
    const float* __restrict__ bias, float* __restrict__ C, int M)
{
    constexpr int BM = 128, BK = 8;
    constexpr int NTH = 16 * (BN / 8);          // 256 for BN=128, 128 for BN=64
    constexpr int A4_TOTAL = BM * BK / 4;       // 256 float4
    constexpr int W4_TOTAL = BK * BN / 4;       // 256 / 128 float4

    __shared__ float As[BK][BM];
    __shared__ float Ws[BK][BN];

    const int tid = threadIdx.x;
    const int tx = tid % (BN / 8);              // col group
    const int ty = tid / (BN / 8);              // row group 0..15
    const int r0 = blockIdx.x * BM;

    float acc[8][8];
#pragma unroll
    for (int i = 0; i < 8; ++i)
#pragma unroll
        for (int j = 0; j < 8; ++j) acc[i][j] = 0.f;

    for (int kt = 0; kt < K; kt += BK) {
        // Load A tile (BM x BK), store transposed As[k][row]
#pragma unroll
        for (int it = 0; it < A4_TOTAL / NTH; ++it) {
            int idx = tid + it * NTH;           // 0..255
            int row = idx >> 1;                 // 0..127
            int kq  = (idx & 1) * 4;            // 0 or 4
            float4 v = make_float4(0.f, 0.f, 0.f, 0.f);
            if (r0 + row < M)
                v = *(const float4*)(A + (size_t)(r0 + row) * K + kt + kq);
            As[kq + 0][row] = v.x;
            As[kq + 1][row] = v.y;
            As[kq + 2][row] = v.z;
            As[kq + 3][row] = v.w;
        }
        // Load W tile (BK x BN)
#pragma unroll
        for (int it = 0; it < W4_TOTAL / NTH; ++it) {
            int idx = tid + it * NTH;
            int kr = idx / (BN / 4);
            int cq = idx % (BN / 4);
            *(float4*)(&Ws[kr][cq * 4]) =
                *(const float4*)(W + (size_t)(kt + kr) * BN + cq * 4);
        }
        __syncthreads();

#pragma unroll
        for (int k = 0; k < BK; ++k) {
            float4 a0 = *(const float4*)(&As[k][ty * 8]);
            float4 a1 = *(const float4*)(&As[k][ty * 8 + 4]);
            float4 w0 = *(const float4*)(&Ws[k][tx * 8]);
            float4 w1 = *(const float4*)(&Ws[k][tx * 8 + 4]);
            float a[8] = {a0.x, a0.y, a0.z, a0.w, a1.x, a1.y, a1.z, a1.w};
            float w[8] = {w0.x, w0.y, w0.z, w0.w, w1.x, w1.y, w1.z, w1.w};
#pragma unroll
            for (int i = 0; i < 8; ++i)
#pragma unroll
                for (int j = 0; j < 8; ++j)
                    acc[i][j] = fmaf(a[i], w[j], acc[i][j]);
        }
        __syncthreads();
    }

    // Epilogue: add bias, store
    float bj[8];
#pragma unroll
    for (int j = 0; j < 8; ++j) bj[j] = bias[tx * 8 + j];
#pragma unroll
    for (int i = 0; i < 8; ++i) {
        int r = r0 + ty * 8 + i;
        if (r < M) {
            float4 o0 = make_float4(acc[i][0] + bj[0], acc[i][1] + bj[1],
                                    acc[i][2] + bj[2], acc[i][3] + bj[3]);
            float4 o1 = make_float4(acc[i][4] + bj[4], acc[i][5] + bj[5],
                                    acc[i][6] + bj[6], acc[i][7] + bj[7]);
            *(float4*)(C + (size_t)r * BN + tx * 8)     = o0;
            *(float4*)(C + (size_t)r * BN + tx * 8 + 4) = o1;
        }
    }
}

// ---------------------------------------------------------------------------
// CSR SpMM, float4 features: out[r,f] = sum_e vals[e] * dense[cols[e], f]
// Thread owns 4 features; F/4 threads per row; 128 threads/block.
// 4-way edge unroll + 2 accumulators for MLP and short FMA chains.
// ---------------------------------------------------------------------------
__device__ __forceinline__ float4 fma4(float s, float4 d, float4 a) {
    a.x = fmaf(s, d.x, a.x); a.y = fmaf(s, d.y, a.y);
    a.z = fmaf(s, d.z, a.z); a.w = fmaf(s, d.w, a.w);
    return a;
}

template <int F, bool RELU>
__global__ __launch_bounds__(128) void spmm_kernel(
    const int* __restrict__ cols, const float* __restrict__ vals,
    const float4* __restrict__ dense, float4* __restrict__ out)
{
    constexpr int F4 = F / 4;
    constexpr int RPB = 128 / F4;
    const int r = blockIdx.x * RPB + threadIdx.x / F4;
    if (r >= N_NODES) return;
    const int f = threadIdx.x % F4;

    int e = g_rp[r];
    const int e_end = g_rp[r + 1];

    float4 acc0 = make_float4(0.f, 0.f, 0.f, 0.f);
    float4 acc1 = make_float4(0.f, 0.f, 0.f, 0.f);

    for (; e + 4 <= e_end; e += 4) {
        int c0 = __ldg(cols + e);
        int c1 = __ldg(cols + e + 1);
        int c2 = __ldg(cols + e + 2);
        int c3 = __ldg(cols + e + 3);
        float v0 = __ldg(vals + e);
        float v1 = __ldg(vals + e + 1);
        float v2 = __ldg(vals + e + 2);
        float v3 = __ldg(vals + e + 3);
        float4 d0 = __ldg(dense + (size_t)c0 * F4 + f);
        float4 d1 = __ldg(dense + (size_t)c1 * F4 + f);
        float4 d2 = __ldg(dense + (size_t)c2 * F4 + f);
        float4 d3 = __ldg(dense + (size_t)c3 * F4 + f);
        acc0 = fma4(v0, d0, acc0);
        acc1 = fma4(v1, d1, acc1);
        acc0 = fma4(v2, d2, acc0);
        acc1 = fma4(v3, d3, acc1);
    }
    for (; e < e_end; ++e) {
        int c = __ldg(cols + e);
        float v = __ldg(vals + e);
        acc0 = fma4(v, __ldg(dense + (size_t)c * F4 + f), acc0);
    }

    float4 s = make_float4(acc0.x + acc1.x, acc0.y + acc1.y,
                           acc0.z + acc1.z, acc0.w + acc1.w);
    if (RELU) {
        s.x = fmaxf(s.x, 0.f); s.y = fmaxf(s.y, 0.f);
        s.z = fmaxf(s.z, 0.f); s.w = fmaxf(s.w, 0.f);
    }
    out[(size_t)r * F4 + f] = s;
}

// ---------------------------------------------------------------------------
// Decode: out[q] = dot(z[src[q]], z[dst[q]]) over OUTF=64 dims. Warp per edge.
// ---------------------------------------------------------------------------
__global__ void decode_kernel(const int* __restrict__ ei,
                              const float* __restrict__ z,
                              float* __restrict__ out, int eq)
{
    int q = blockIdx.x * 8 + (threadIdx.x >> 5);
    if (q >= eq) return;
    int lane = threadIdx.x & 31;
    int s = __ldg(ei + q);
    int d = __ldg(ei + eq + q);
    const float* zs = z + (size_t)s * OUTF;
    const float* zd = z + (size_t)d * OUTF;
    float p = zs[lane] * zd[lane] + zs[lane + 32] * zd[lane + 32];
#pragma unroll
    for (int o = 16; o > 0; o >>= 1) p += __shfl_down_sync(0xffffffffu, p, o);
    if (lane == 0) out[q] = p;
}

// ---------------------------------------------------------------------------
// Launch
// ---------------------------------------------------------------------------
extern "C" void kernel_launch(void* const* d_in, const int* in_sizes, int n_in,
                              void* d_out, int out_size)
{
    const float* x        = (const float*)d_in[0];   // [N, 256]
    const int*   adj_rows = (const int*)  d_in[1];   // [NNZ] sorted
    const int*   adj_cols = (const int*)  d_in[2];   // [NNZ]
    const float* adj_vals = (const float*)d_in[3];   // [NNZ]
    const int*   edge_idx = (const int*)  d_in[4];   // [2, EQ]
    const float* W1       = (const float*)d_in[5];   // [256, 128]
    const float* b1       = (const float*)d_in[6];   // [128]
    const float* W2       = (const float*)d_in[7];   // [128, 64]
    const float* b2       = (const float*)d_in[8];   // [64]
    float* out = (float*)d_out;                      // [EQ]

    const int nnz = in_sizes[1];
    const int eq  = in_sizes[4] / 2;
    const int M   = N_NODES;

    float* h0 = nullptr; cudaGetSymbolAddress((void**)&h0, g_h0);
    float* h  = nullptr; cudaGetSymbolAddress((void**)&h,  g_h);
    float* z0 = nullptr; cudaGetSymbolAddress((void**)&z0, g_z0);
    float* z  = nullptr; cudaGetSymbolAddress((void**)&z,  g_z);

    // 1. row pointers from sorted rows
    build_rowptr_kernel<<<(nnz + 255) / 256, 256>>>(adj_rows, nnz);

    // 2. h0 = x @ W1 + b1   (BM=128, BN=128, 256 threads)
    gemm_bias_kernel<IN_F, HID><<<(M + 127) / 128, 256>>>(x, W1, b1, h0, M);

    // 3. h = relu(spmm(h0))  (HID=128 -> 32 thr/row, 4 rows/block)
    spmm_kernel<HID, true><<<(M + 3) / 4, 128>>>(
        adj_cols, adj_vals, (const float4*)h0, (float4*)h);

    // 4. z0 = h @ W2 + b2    (BM=128, BN=64, 128 threads)
    gemm_bias_kernel<HID, OUTF><<<(M + 127) / 128, 128>>>(h, W2, b2, z0, M);

    // 5. z = spmm(z0)        (OUTF=64 -> 16 thr/row, 8 rows/block)
    spmm_kernel<OUTF, false><<<(M + 7) / 8, 128>>>(
        adj_cols, adj_vals, (const float4*)z0, (float4*)z);

    // 6. edge dot products
    decode_kernel<<<(eq + 7) / 8, 256>>>(edge_idx, z, out, eq);
}

// round 7
// speedup vs baseline: 1.6867x; 1.2145x over previous
#include <cuda_runtime.h>
#include <cuda_bf16.h>
#include <cstdint>

// Problem constants
#define N_NODES 100000
#define IN_F    256
#define HID     128
#define OUTF    64

// Scratch (device globals — no allocation allowed)
__device__ float g_h0[(size_t)N_NODES * HID];   // x@W1+b1
__device__ float g_h [(size_t)N_NODES * HID];   // relu(spmm(h0))
__device__ float g_z0[(size_t)N_NODES * OUTF];  // h@W2+b2
__device__ float g_z [(size_t)N_NODES * OUTF];  // spmm(z0)
__device__ int   g_rp[N_NODES + 1];             // CSR row pointers

// ===========================================================================
// Build CSR row_ptr from the sorted rows array.
// ===========================================================================
__global__ void build_rowptr_kernel(const int* __restrict__ rows, int nnz) {
    int e = blockIdx.x * blockDim.x + threadIdx.x;
    if (e >= nnz) return;
    int r = rows[e];
    int rprev = (e == 0) ? -1 : rows[e - 1];
    for (int rr = rprev + 1; rr <= r; ++rr) g_rp[rr] = e;
    if (e == nnz - 1) {
        for (int rr = r + 1; rr <= N_NODES; ++rr) g_rp[rr] = nnz;
    }
}

// ===========================================================================
// mma.sync m16n8k16 bf16 -> fp32 accumulate
// ===========================================================================
__device__ __forceinline__ void mma_bf16(float* c, const uint32_t* a,
                                         uint32_t b0, uint32_t b1) {
    asm volatile(
        "mma.sync.aligned.m16n8k16.row.col.f32.bf16.bf16.f32 "
        "{%0,%1,%2,%3}, {%4,%5,%6,%7}, {%8,%9}, {%0,%1,%2,%3};"
        : "+f"(c[0]), "+f"(c[1]), "+f"(c[2]), "+f"(c[3])
        : "r"(a[0]), "r"(a[1]), "r"(a[2]), "r"(a[3]), "r"(b0), "r"(b1));
}

// ===========================================================================
// Split-bf16 GEMM + bias via mma.sync: C[M,BN] = A[M,K] @ W[K,BN] + b
// fp32-accurate: each operand split hi/lo bf16; acc += Ahi*Bhi+Ahi*Blo+Alo*Bhi.
// CTA: 128 x BN, BK=64 chunks. 8 warps in 4(m) x 2(n); warp tile 32 x BN/2.
// Smem: padded (stride 72 bf16) row-major tiles, conflict-free LDS fragments.
// ===========================================================================
template <int K_TOTAL, int BN>
__global__ __launch_bounds__(256) void mma_gemm_bias(
    const float* __restrict__ A, const float* __restrict__ W,
    const float* __restrict__ bias, float* __restrict__ C, int M)
{
    constexpr int BM = 128, BK = 64, LDSW = 72;
    constexpr int CHUNKS = K_TOTAL / BK;
    constexpr int WN = BN / 2;          // warp n extent
    constexpr int NT = WN / 8;          // n-tiles per warp (8 or 4)
    constexpr int MT = 2;               // m-tiles per warp (2 x 16 = 32 rows)

    extern __shared__ __nv_bfloat16 sm[];
    __nv_bfloat16* Ah = sm;                      // [BM][LDSW]
    __nv_bfloat16* Al = sm + BM * LDSW;
    __nv_bfloat16* Bh = sm + 2 * BM * LDSW;      // [BN][LDSW] (Bs[n][k])
    __nv_bfloat16* Bl = Bh + BN * LDSW;

    const int tid = threadIdx.x;
    const int wid = tid >> 5;
    const int lane = tid & 31;
    const int wm = wid >> 1;            // 0..3
    const int wn = wid & 1;             // 0..1
    const int lr = lane >> 2;           // 0..7 row-in-8
    const int lc = lane & 3;            // 0..3 k-pair
    const int r0 = blockIdx.x * BM;

    float acc[MT][NT][4];
#pragma unroll
    for (int i = 0; i < MT; ++i)
#pragma unroll
        for (int j = 0; j < NT; ++j)
#pragma unroll
            for (int q = 0; q < 4; ++q) acc[i][j][q] = 0.f;

    for (int kc = 0; kc < CHUNKS; ++kc) {
        if (kc) __syncthreads();        // protect smem reuse

        // ---- load + split A chunk: 128 rows x 64 K, float4 per thread x8 ----
#pragma unroll
        for (int it = 0; it < 8; ++it) {
            int idx = tid + it * 256;   // 0..2047
            int row = idx >> 4;         // 0..127
            int j4 = (idx & 15) * 4;    // 0..60
            float4 v = make_float4(0.f, 0.f, 0.f, 0.f);
            if (r0 + row < M)
                v = *(const float4*)(A + (size_t)(r0 + row) * K_TOTAL + kc * BK + j4);
            __nv_bfloat162 h01 = __floats2bfloat162_rn(v.x, v.y);
            __nv_bfloat162 h23 = __floats2bfloat162_rn(v.z, v.w);
            __nv_bfloat162 l01 = __floats2bfloat162_rn(
                v.x - __bfloat162float(h01.x), v.y - __bfloat162float(h01.y));
            __nv_bfloat162 l23 = __floats2bfloat162_rn(
                v.z - __bfloat162float(h23.x), v.w - __bfloat162float(h23.y));
            int o = row * LDSW + j4;
            *(__nv_bfloat162*)(Ah + o)     = h01;
            *(__nv_bfloat162*)(Ah + o + 2) = h23;
            *(__nv_bfloat162*)(Al + o)     = l01;
            *(__nv_bfloat162*)(Al + o + 2) = l23;
        }
        // ---- load + transpose + split B chunk: Bs[n][k] = W[kc*64+k][n] ----
#pragma unroll
        for (int it = 0; it < (BK * BN) / 256; ++it) {
            int idx = tid + it * 256;
            int kl = idx / BN;          // 0..63
            int n  = idx % BN;          // coalesced over n
            float w = __ldg(W + (size_t)(kc * BK + kl) * BN + n);
            __nv_bfloat16 hi = __float2bfloat16(w);
            __nv_bfloat16 lo = __float2bfloat16(w - __bfloat162float(hi));
            Bh[n * LDSW + kl] = hi;
            Bl[n * LDSW + kl] = lo;
        }
        __syncthreads();

        // ---- MMA inner loop: 4 k16 steps per chunk ----
#pragma unroll
        for (int ks = 0; ks < BK / 16; ++ks) {
            const int k0 = ks * 16;
            uint32_t ah[MT][4], al[MT][4];
#pragma unroll
            for (int i = 0; i < MT; ++i) {
                const __nv_bfloat16* pa = Ah + (wm * 32 + i * 16 + lr) * LDSW + k0 + 2 * lc;
                const __nv_bfloat16* pl = Al + (wm * 32 + i * 16 + lr) * LDSW + k0 + 2 * lc;
                ah[i][0] = *(const uint32_t*)pa;
                ah[i][1] = *(const uint32_t*)(pa + 8 * LDSW);
                ah[i][2] = *(const uint32_t*)(pa + 8);
                ah[i][3] = *(const uint32_t*)(pa + 8 * LDSW + 8);
                al[i][0] = *(const uint32_t*)pl;
                al[i][1] = *(const uint32_t*)(pl + 8 * LDSW);
                al[i][2] = *(const uint32_t*)(pl + 8);
                al[i][3] = *(const uint32_t*)(pl + 8 * LDSW + 8);
            }
#pragma unroll
            for (int j = 0; j < NT; ++j) {
                const __nv_bfloat16* pb = Bh + (wn * WN + j * 8 + lr) * LDSW + k0 + 2 * lc;
                const __nv_bfloat16* pbl = Bl + (wn * WN + j * 8 + lr) * LDSW + k0 + 2 * lc;
                uint32_t bh0 = *(const uint32_t*)pb;
                uint32_t bh1 = *(const uint32_t*)(pb + 8);
                uint32_t bl0 = *(const uint32_t*)pbl;
                uint32_t bl1 = *(const uint32_t*)(pbl + 8);
#pragma unroll
                for (int i = 0; i < MT; ++i) {
                    mma_bf16(acc[i][j], ah[i], bh0, bh1);   // hi*hi
                    mma_bf16(acc[i][j], ah[i], bl0, bl1);   // hi*lo
                    mma_bf16(acc[i][j], al[i], bh0, bh1);   // lo*hi
                }
            }
        }
    }

    // ---- epilogue: bias add + store (float2 per half-tile) ----
#pragma unroll
    for (int j = 0; j < NT; ++j) {
        int col = wn * WN + j * 8 + 2 * lc;
        float bb0 = __ldg(bias + col);
        float bb1 = __ldg(bias + col + 1);
#pragma unroll
        for (int i = 0; i < MT; ++i) {
            int row = r0 + wm * 32 + i * 16 + lr;
            if (row < M) {
                float2 o = make_float2(acc[i][j][0] + bb0, acc[i][j][1] + bb1);
                *(float2*)(C + (size_t)row * BN + col) = o;
            }
            if (row + 8 < M) {
                float2 o = make_float2(acc[i][j][2] + bb0, acc[i][j][3] + bb1);
                *(float2*)(C + (size_t)(row + 8) * BN + col) = o;
            }
        }
    }
}

// ===========================================================================
// CSR SpMM, float4 features (unchanged — near L2 roofline)
// ===========================================================================
__device__ __forceinline__ float4 fma4(float s, float4 d, float4 a) {
    a.x = fmaf(s, d.x, a.x); a.y = fmaf(s, d.y, a.y);
    a.z = fmaf(s, d.z, a.z); a.w = fmaf(s, d.w, a.w);
    return a;
}

template <int F, bool RELU>
__global__ __launch_bounds__(128) void spmm_kernel(
    const int* __restrict__ cols, const float* __restrict__ vals,
    const float4* __restrict__ dense, float4* __restrict__ out)
{
    constexpr int F4 = F / 4;
    constexpr int RPB = 128 / F4;
    const int r = blockIdx.x * RPB + threadIdx.x / F4;
    if (r >= N_NODES) return;
    const int f = threadIdx.x % F4;

    int e = g_rp[r];
    const int e_end = g_rp[r + 1];

    float4 acc0 = make_float4(0.f, 0.f, 0.f, 0.f);
    float4 acc1 = make_float4(0.f, 0.f, 0.f, 0.f);

    for (; e + 4 <= e_end; e += 4) {
        int c0 = __ldg(cols + e);
        int c1 = __ldg(cols + e + 1);
        int c2 = __ldg(cols + e + 2);
        int c3 = __ldg(cols + e + 3);
        float v0 = __ldg(vals + e);
        float v1 = __ldg(vals + e + 1);
        float v2 = __ldg(vals + e + 2);
        float v3 = __ldg(vals + e + 3);
        float4 d0 = __ldg(dense + (size_t)c0 * F4 + f);
        float4 d1 = __ldg(dense + (size_t)c1 * F4 + f);
        float4 d2 = __ldg(dense + (size_t)c2 * F4 + f);
        float4 d3 = __ldg(dense + (size_t)c3 * F4 + f);
        acc0 = fma4(v0, d0, acc0);
        acc1 = fma4(v1, d1, acc1);
        acc0 = fma4(v2, d2, acc0);
        acc1 = fma4(v3, d3, acc1);
    }
    for (; e < e_end; ++e) {
        int c = __ldg(cols + e);
        float v = __ldg(vals + e);
        acc0 = fma4(v, __ldg(dense + (size_t)c * F4 + f), acc0);
    }

    float4 s = make_float4(acc0.x + acc1.x, acc0.y + acc1.y,
                           acc0.z + acc1.z, acc0.w + acc1.w);
    if (RELU) {
        s.x = fmaxf(s.x, 0.f); s.y = fmaxf(s.y, 0.f);
        s.z = fmaxf(s.z, 0.f); s.w = fmaxf(s.w, 0.f);
    }
    out[(size_t)r * F4 + f] = s;
}

// ===========================================================================
// Decode: out[q] = dot(z[src[q]], z[dst[q]]) over OUTF=64. Warp per edge.
// ===========================================================================
__global__ void decode_kernel(const int* __restrict__ ei,
                              const float* __restrict__ z,
                              float* __restrict__ out, int eq)
{
    int q = blockIdx.x * 8 + (threadIdx.x >> 5);
    if (q >= eq) return;
    int lane = threadIdx.x & 31;
    int s = __ldg(ei + q);
    int d = __ldg(ei + eq + q);
    const float* zs = z + (size_t)s * OUTF;
    const float* zd = z + (size_t)d * OUTF;
    float p = zs[lane] * zd[lane] + zs[lane + 32] * zd[lane + 32];
#pragma unroll
    for (int o = 16; o > 0; o >>= 1) p += __shfl_down_sync(0xffffffffu, p, o);
    if (lane == 0) out[q] = p;
}

// ===========================================================================
// Launch
// ===========================================================================
extern "C" void kernel_launch(void* const* d_in, const int* in_sizes, int n_in,
                              void* d_out, int out_size)
{
    const float* x        = (const float*)d_in[0];   // [N, 256]
    const int*   adj_rows = (const int*)  d_in[1];   // [NNZ] sorted
    const int*   adj_cols = (const int*)  d_in[2];   // [NNZ]
    const float* adj_vals = (const float*)d_in[3];   // [NNZ]
    const int*   edge_idx = (const int*)  d_in[4];   // [2, EQ]
    const float* W1       = (const float*)d_in[5];   // [256, 128]
    const float* b1       = (const float*)d_in[6];   // [128]
    const float* W2       = (const float*)d_in[7];   // [128, 64]
    const float* b2       = (const float*)d_in[8];   // [64]
    float* out = (float*)d_out;                      // [EQ]

    const int nnz = in_sizes[1];
    const int eq  = in_sizes[4] / 2;
    const int M   = N_NODES;

    float* h0 = nullptr; cudaGetSymbolAddress((void**)&h0, g_h0);
    float* h  = nullptr; cudaGetSymbolAddress((void**)&h,  g_h);
    float* z0 = nullptr; cudaGetSymbolAddress((void**)&z0, g_z0);
    float* z  = nullptr; cudaGetSymbolAddress((void**)&z,  g_z);

    // Dynamic smem: (2*BM + 2*BN) * 72 bf16 elems * 2 bytes
    constexpr int SMEM1 = (2 * 128 + 2 * 128) * 72 * 2;  // 73728 (BN=128)
    constexpr int SMEM2 = (2 * 128 + 2 * 64) * 72 * 2;   // 55296 (BN=64)
    cudaFuncSetAttribute(mma_gemm_bias<IN_F, HID>,
                         cudaFuncAttributeMaxDynamicSharedMemorySize, SMEM1);
    cudaFuncSetAttribute(mma_gemm_bias<HID, OUTF>,
                         cudaFuncAttributeMaxDynamicSharedMemorySize, SMEM2);

    const int gblocks = (M + 127) / 128;   // 782

    // 1. row pointers from sorted rows
    build_rowptr_kernel<<<(nnz + 255) / 256, 256>>>(adj_rows, nnz);

    // 2. h0 = x @ W1 + b1   (split-bf16 mma.sync)
    mma_gemm_bias<IN_F, HID><<<gblocks, 256, SMEM1>>>(x, W1, b1, h0, M);

    // 3. h = relu(spmm(h0))
    spmm_kernel<HID, true><<<(M + 3) / 4, 128>>>(
        adj_cols, adj_vals, (const float4*)h0, (float4*)h);

    // 4. z0 = h @ W2 + b2   (split-bf16 mma.sync)
    mma_gemm_bias<HID, OUTF><<<gblocks, 256, SMEM2>>>(h, W2, b2, z0, M);

    // 5. z = spmm(z0)
    spmm_kernel<OUTF, false><<<(M + 7) / 8, 128>>>(
        adj_cols, adj_vals, (const float4*)z0, (float4*)z);

    // 6. edge dot products
    decode_kernel<<<(eq + 7) / 8, 256>>>(edge_idx, z, out, eq);
}

// round 10
// speedup vs baseline: 1.9077x; 1.1310x over previous
#include <cuda_runtime.h>
#include <cuda_bf16.h>
#include <cstdint>

// Problem constants
#define N_NODES 100000
#define IN_F    256
#define HID     128
#define OUTF    64

// Scratch (device globals — no allocation allowed)
__device__ float g_h0[(size_t)N_NODES * HID];   // x@W1+b1
__device__ float g_h [(size_t)N_NODES * HID];   // relu(spmm(h0))
__device__ float g_z0[(size_t)N_NODES * OUTF];  // h@W2+b2
__device__ float g_z [(size_t)N_NODES * OUTF];  // spmm(z0)
__device__ int   g_rp[N_NODES + 1];             // CSR row pointers

// ===========================================================================
// Build CSR row_ptr from the sorted rows array.
// ===========================================================================
__global__ void build_rowptr_kernel(const int* __restrict__ rows, int nnz) {
    int e = blockIdx.x * blockDim.x + threadIdx.x;
    if (e >= nnz) return;
    int r = rows[e];
    int rprev = (e == 0) ? -1 : rows[e - 1];
    for (int rr = rprev + 1; rr <= r; ++rr) g_rp[rr] = e;
    if (e == nnz - 1) {
        for (int rr = r + 1; rr <= N_NODES; ++rr) g_rp[rr] = nnz;
    }
}

// ===========================================================================
// mma.sync m16n8k16 bf16 -> fp32 accumulate, ldmatrix loaders
// ===========================================================================
__device__ __forceinline__ void mma_bf16(float* c, const uint32_t* a,
                                         uint32_t b0, uint32_t b1) {
    asm volatile(
        "mma.sync.aligned.m16n8k16.row.col.f32.bf16.bf16.f32 "
        "{%0,%1,%2,%3}, {%4,%5,%6,%7}, {%8,%9}, {%0,%1,%2,%3};"
        : "+f"(c[0]), "+f"(c[1]), "+f"(c[2]), "+f"(c[3])
        : "r"(a[0]), "r"(a[1]), "r"(a[2]), "r"(a[3]), "r"(b0), "r"(b1));
}
__device__ __forceinline__ void ldsm_x4(uint32_t* r, uint32_t addr) {
    asm volatile("ldmatrix.sync.aligned.m8n8.x4.shared.b16 {%0,%1,%2,%3}, [%4];"
                 : "=r"(r[0]), "=r"(r[1]), "=r"(r[2]), "=r"(r[3]) : "r"(addr));
}
__device__ __forceinline__ void ldsm_x2(uint32_t* r, uint32_t addr) {
    asm volatile("ldmatrix.sync.aligned.m8n8.x2.shared.b16 {%0,%1}, [%2];"
                 : "=r"(r[0]), "=r"(r[1]) : "r"(addr));
}

// ===========================================================================
// Split-bf16 GEMM + bias via mma.sync + ldmatrix.
// C[M,BN] = A[M,K] @ W[K,BN] + b, fp32-accurate (hi*hi + hi*lo + lo*hi).
// CTA: 128 x BN, BK=64 chunks. 8 warps 4(m) x 2(n); warp tile 32 x BN/2.
// Smem tiles padded to 72 bf16 stride (144B) -> ldmatrix conflict-free.
// ===========================================================================
template <int K_TOTAL, int BN>
__global__ __launch_bounds__(256) void mma_gemm_bias(
    const float* __restrict__ A, const float* __restrict__ W,
    const float* __restrict__ bias, float* __restrict__ C, int M)
{
    constexpr int BM = 128, BK = 64, LDSW = 72;
    constexpr int CHUNKS = K_TOTAL / BK;
    constexpr int WN = BN / 2;          // warp n extent
    constexpr int NT = WN / 8;          // n-tiles per warp
    constexpr int MT = 2;               // m-tiles per warp (32 rows)

    extern __shared__ __nv_bfloat16 sm[];
    __nv_bfloat16* Ah = sm;                      // [BM][LDSW]
    __nv_bfloat16* Al = sm + BM * LDSW;
    __nv_bfloat16* Bh = sm + 2 * BM * LDSW;      // [BN][LDSW]  (Bs[n][k])
    __nv_bfloat16* Bl = Bh + BN * LDSW;

    const int tid = threadIdx.x;
    const int wid = tid >> 5;
    const int lane = tid & 31;
    const int wm = wid >> 1;            // 0..3
    const int wn = wid & 1;             // 0..1
    const int lr = lane >> 2;           // 0..7
    const int lc = lane & 3;            // 0..3
    const int r0 = blockIdx.x * BM;

    // ldmatrix lane-address components
    const int m4    = lane >> 3;                    // which 8x8 matrix
    const int arow  = (lane & 7) + (m4 & 1) * 8;    // A row within 16-row tile
    const int akoff = (m4 >> 1) * 8;                // A k offset (0 or 8)
    const int brow  = lane & 7;                     // B n row within 8
    const int bkoff = ((lane >> 3) & 1) * 8;        // B k offset (0 or 8)

    const uint32_t AhB = (uint32_t)__cvta_generic_to_shared(Ah) +
                         ((wm * 32 + arow) * LDSW + akoff) * 2;
    const uint32_t AlB = (uint32_t)__cvta_generic_to_shared(Al) +
                         ((wm * 32 + arow) * LDSW + akoff) * 2;
    const uint32_t BhB = (uint32_t)__cvta_generic_to_shared(Bh) +
                         ((wn * WN + brow) * LDSW + bkoff) * 2;
    const uint32_t BlB = (uint32_t)__cvta_generic_to_shared(Bl) +
                         ((wn * WN + brow) * LDSW + bkoff) * 2;

    float acc[MT][NT][4];
#pragma unroll
    for (int i = 0; i < MT; ++i)
#pragma unroll
        for (int j = 0; j < NT; ++j)
#pragma unroll
            for (int q = 0; q < 4; ++q) acc[i][j][q] = 0.f;

    for (int kc = 0; kc < CHUNKS; ++kc) {
        if (kc) __syncthreads();        // protect smem reuse

        // ---- load + split A chunk: 128 rows x 64 K ----
#pragma unroll
        for (int it = 0; it < 8; ++it) {
            int idx = tid + it * 256;   // 0..2047
            int row = idx >> 4;         // 0..127
            int j4 = (idx & 15) * 4;    // 0..60
            float4 v = make_float4(0.f, 0.f, 0.f, 0.f);
            if (r0 + row < M)
                v = *(const float4*)(A + (size_t)(r0 + row) * K_TOTAL + kc * BK + j4);
            __nv_bfloat162 h01 = __floats2bfloat162_rn(v.x, v.y);
            __nv_bfloat162 h23 = __floats2bfloat162_rn(v.z, v.w);
            __nv_bfloat162 l01 = __floats2bfloat162_rn(
                v.x - __bfloat162float(h01.x), v.y - __bfloat162float(h01.y));
            __nv_bfloat162 l23 = __floats2bfloat162_rn(
                v.z - __bfloat162float(h23.x), v.w - __bfloat162float(h23.y));
            int o = row * LDSW + j4;
            *(__nv_bfloat162*)(Ah + o)     = h01;
            *(__nv_bfloat162*)(Ah + o + 2) = h23;
            *(__nv_bfloat162*)(Al + o)     = l01;
            *(__nv_bfloat162*)(Al + o + 2) = l23;
        }
        // ---- load + transpose + split B chunk: Bs[n][k] = W[kc*64+k][n] ----
#pragma unroll
        for (int it = 0; it < (BK * BN) / 256; ++it) {
            int idx = tid + it * 256;
            int kl = idx / BN;          // 0..63
            int n  = idx % BN;          // coalesced over n
            float w = __ldg(W + (size_t)(kc * BK + kl) * BN + n);
            __nv_bfloat16 hi = __float2bfloat16(w);
            __nv_bfloat16 lo = __float2bfloat16(w - __bfloat162float(hi));
            Bh[n * LDSW + kl] = hi;
            Bl[n * LDSW + kl] = lo;
        }
        __syncthreads();

        // ---- MMA inner loop: 4 k16 steps per chunk ----
#pragma unroll
        for (int ks = 0; ks < BK / 16; ++ks) {
            const int k0 = ks * 16;
            uint32_t ah[MT][4], al[MT][4];
#pragma unroll
            for (int i = 0; i < MT; ++i) {
                ldsm_x4(ah[i], AhB + (i * 16 * LDSW + k0) * 2);
                ldsm_x4(al[i], AlB + (i * 16 * LDSW + k0) * 2);
            }
#pragma unroll
            for (int j = 0; j < NT; ++j) {
                uint32_t bh[2], bl[2];
                ldsm_x2(bh, BhB + (j * 8 * LDSW + k0) * 2);
                ldsm_x2(bl, BlB + (j * 8 * LDSW + k0) * 2);
#pragma unroll
                for (int i = 0; i < MT; ++i) {
                    mma_bf16(acc[i][j], ah[i], bh[0], bh[1]);   // hi*hi
                    mma_bf16(acc[i][j], ah[i], bl[0], bl[1]);   // hi*lo
                    mma_bf16(acc[i][j], al[i], bh[0], bh[1]);   // lo*hi
                }
            }
        }
    }

    // ---- epilogue: bias add + store ----
#pragma unroll
    for (int j = 0; j < NT; ++j) {
        int col = wn * WN + j * 8 + 2 * lc;
        float bb0 = __ldg(bias + col);
        float bb1 = __ldg(bias + col + 1);
#pragma unroll
        for (int i = 0; i < MT; ++i) {
            int row = r0 + wm * 32 + i * 16 + lr;
            if (row < M) {
                float2 o = make_float2(acc[i][j][0] + bb0, acc[i][j][1] + bb1);
                *(float2*)(C + (size_t)row * BN + col) = o;
            }
            if (row + 8 < M) {
                float2 o = make_float2(acc[i][j][2] + bb0, acc[i][j][3] + bb1);
                *(float2*)(C + (size_t)(row + 8) * BN + col) = o;
            }
        }
    }
}

// ===========================================================================
// CSR SpMM, float4 features, 8-way edge unroll for deeper gather MLP.
// ===========================================================================
__device__ __forceinline__ float4 fma4(float s, float4 d, float4 a) {
    a.x = fmaf(s, d.x, a.x); a.y = fmaf(s, d.y, a.y);
    a.z = fmaf(s, d.z, a.z); a.w = fmaf(s, d.w, a.w);
    return a;
}

template <int F, bool RELU>
__global__ __launch_bounds__(128) void spmm_kernel(
    const int* __restrict__ cols, const float* __restrict__ vals,
    const float4* __restrict__ dense, float4* __restrict__ out)
{
    constexpr int F4 = F / 4;
    constexpr int RPB = 128 / F4;
    const int r = blockIdx.x * RPB + threadIdx.x / F4;
    if (r >= N_NODES) return;
    const int f = threadIdx.x % F4;

    int e = g_rp[r];
    const int e_end = g_rp[r + 1];

    float4 acc0 = make_float4(0.f, 0.f, 0.f, 0.f);
    float4 acc1 = make_float4(0.f, 0.f, 0.f, 0.f);

    // 8-way unrolled main loop: 8 gathers in flight per thread
    for (; e + 8 <= e_end; e += 8) {
        int   c[8];
        float v[8];
#pragma unroll
        for (int u = 0; u < 8; ++u) c[u] = __ldg(cols + e + u);
#pragma unroll
        for (int u = 0; u < 8; ++u) v[u] = __ldg(vals + e + u);
        float4 d[8];
#pragma unroll
        for (int u = 0; u < 8; ++u) d[u] = __ldg(dense + (size_t)c[u] * F4 + f);
#pragma unroll
        for (int u = 0; u < 8; u += 2) {
            acc0 = fma4(v[u],     d[u],     acc0);
            acc1 = fma4(v[u + 1], d[u + 1], acc1);
        }
    }
    // 4-way
    for (; e + 4 <= e_end; e += 4) {
        int c0 = __ldg(cols + e),     c1 = __ldg(cols + e + 1);
        int c2 = __ldg(cols + e + 2), c3 = __ldg(cols + e + 3);
        float v0 = __ldg(vals + e),     v1 = __ldg(vals + e + 1);
        float v2 = __ldg(vals + e + 2), v3 = __ldg(vals + e + 3);
        float4 d0 = __ldg(dense + (size_t)c0 * F4 + f);
        float4 d1 = __ldg(dense + (size_t)c1 * F4 + f);
        float4 d2 = __ldg(dense + (size_t)c2 * F4 + f);
        float4 d3 = __ldg(dense + (size_t)c3 * F4 + f);
        acc0 = fma4(v0, d0, acc0);
        acc1 = fma4(v1, d1, acc1);
        acc0 = fma4(v2, d2, acc0);
        acc1 = fma4(v3, d3, acc1);
    }
    // scalar tail
    for (; e < e_end; ++e) {
        int c = __ldg(cols + e);
        float v = __ldg(vals + e);
        acc0 = fma4(v, __ldg(dense + (size_t)c * F4 + f), acc0);
    }

    float4 s = make_float4(acc0.x + acc1.x, acc0.y + acc1.y,
                           acc0.z + acc1.z, acc0.w + acc1.w);
    if (RELU) {
        s.x = fmaxf(s.x, 0.f); s.y = fmaxf(s.y, 0.f);
        s.z = fmaxf(s.z, 0.f); s.w = fmaxf(s.w, 0.f);
    }
    out[(size_t)r * F4 + f] = s;
}

// ===========================================================================
// Decode: out[q] = dot(z[src[q]], z[dst[q]]) over OUTF=64. Warp per edge.
// ===========================================================================
__global__ void decode_kernel(const int* __restrict__ ei,
                              const float* __restrict__ z,
                              float* __restrict__ out, int eq)
{
    int q = blockIdx.x * 8 + (threadIdx.x >> 5);
    if (q >= eq) return;
    int lane = threadIdx.x & 31;
    int s = __ldg(ei + q);
    int d = __ldg(ei + eq + q);
    const float* zs = z + (size_t)s * OUTF;
    const float* zd = z + (size_t)d * OUTF;
    float p = zs[lane] * zd[lane] + zs[lane + 32] * zd[lane + 32];
#pragma unroll
    for (int o = 16; o > 0; o >>= 1) p += __shfl_down_sync(0xffffffffu, p, o);
    if (lane == 0) out[q] = p;
}

// ===========================================================================
// Launch
// ===========================================================================
extern "C" void kernel_launch(void* const* d_in, const int* in_sizes, int n_in,
                              void* d_out, int out_size)
{
    const float* x        = (const float*)d_in[0];   // [N, 256]
    const int*   adj_rows = (const int*)  d_in[1];   // [NNZ] sorted
    const int*   adj_cols = (const int*)  d_in[2];   // [NNZ]
    const float* adj_vals = (const float*)d_in[3];   // [NNZ]
    const int*   edge_idx = (const int*)  d_in[4];   // [2, EQ]
    const float* W1       = (const float*)d_in[5];   // [256, 128]
    const float* b1       = (const float*)d_in[6];   // [128]
    const float* W2       = (const float*)d_in[7];   // [128, 64]
    const float* b2       = (const float*)d_in[8];   // [64]
    float* out = (float*)d_out;                      // [EQ]

    const int nnz = in_sizes[1];
    const int eq  = in_sizes[4] / 2;
    const int M   = N_NODES;

    float* h0 = nullptr; cudaGetSymbolAddress((void**)&h0, g_h0);
    float* h  = nullptr; cudaGetSymbolAddress((void**)&h,  g_h);
    float* z0 = nullptr; cudaGetSymbolAddress((void**)&z0, g_z0);
    float* z  = nullptr; cudaGetSymbolAddress((void**)&z,  g_z);

    // Dynamic smem: (2*BM + 2*BN) * 72 bf16 elems * 2 bytes
    constexpr int SMEM1 = (2 * 128 + 2 * 128) * 72 * 2;  // 73728 (BN=128)
    constexpr int SMEM2 = (2 * 128 + 2 * 64) * 72 * 2;   // 55296 (BN=64)
    cudaFuncSetAttribute(mma_gemm_bias<IN_F, HID>,
                         cudaFuncAttributeMaxDynamicSharedMemorySize, SMEM1);
    cudaFuncSetAttribute(mma_gemm_bias<HID, OUTF>,
                         cudaFuncAttributeMaxDynamicSharedMemorySize, SMEM2);

    const int gblocks = (M + 127) / 128;   // 782

    // 1. row pointers from sorted rows
    build_rowptr_kernel<<<(nnz + 255) / 256, 256>>>(adj_rows, nnz);

    // 2. h0 = x @ W1 + b1   (split-bf16 mma.sync + ldmatrix)
    mma_gemm_bias<IN_F, HID><<<gblocks, 256, SMEM1>>>(x, W1, b1, h0, M);

    // 3. h = relu(spmm(h0))
    spmm_kernel<HID, true><<<(M + 3) / 4, 128>>>(
        adj_cols, adj_vals, (const float4*)h0, (float4*)h);

    // 4. z0 = h @ W2 + b2   (split-bf16 mma.sync + ldmatrix)
    mma_gemm_bias<HID, OUTF><<<gblocks, 256, SMEM2>>>(h, W2, b2, z0, M);

    // 5. z = spmm(z0)
    spmm_kernel<OUTF, false><<<(M + 7) / 8, 128>>>(
        adj_cols, adj_vals, (const float4*)z0, (float4*)z);

    // 6. edge dot products
    decode_kernel<<<(eq + 7) / 8, 256>>>(edge_idx, z, out, eq);
}

// round 12
// speedup vs baseline: 2.0970x; 1.0992x over previous
#include <cuda_runtime.h>
#include <cuda_bf16.h>
#include <cuda_fp16.h>
#include <cstdint>

// Problem constants
#define N_NODES 100000
#define IN_F    256
#define HID     128
#define OUTF    64

// Scratch (device globals — no allocation allowed).
// h0 / z0 stored as fp16 (uint4-aligned) — only consumed by the SpMM gathers.
__device__ uint4 g_h0h[(size_t)N_NODES * HID / 8];   // x@W1+b1   (fp16)
__device__ float g_h [(size_t)N_NODES * HID];        // relu(spmm(h0)) fp32
__device__ uint4 g_z0h[(size_t)N_NODES * OUTF / 8];  // h@W2+b2   (fp16)
__device__ float g_z [(size_t)N_NODES * OUTF];       // spmm(z0)  fp32
__device__ int   g_rp[N_NODES + 1];                  // CSR row pointers

// ===========================================================================
// Build CSR row_ptr from the sorted rows array.
// ===========================================================================
__global__ void build_rowptr_kernel(const int* __restrict__ rows, int nnz) {
    int e = blockIdx.x * blockDim.x + threadIdx.x;
    if (e >= nnz) return;
    int r = rows[e];
    int rprev = (e == 0) ? -1 : rows[e - 1];
    for (int rr = rprev + 1; rr <= r; ++rr) g_rp[rr] = e;
    if (e == nnz - 1) {
        for (int rr = r + 1; rr <= N_NODES; ++rr) g_rp[rr] = nnz;
    }
}

// ===========================================================================
// mma.sync m16n8k16 bf16 -> fp32 accumulate, ldmatrix loaders
// ===========================================================================
__device__ __forceinline__ void mma_bf16(float* c, const uint32_t* a,
                                         uint32_t b0, uint32_t b1) {
    asm volatile(
        "mma.sync.aligned.m16n8k16.row.col.f32.bf16.bf16.f32 "
        "{%0,%1,%2,%3}, {%4,%5,%6,%7}, {%8,%9}, {%0,%1,%2,%3};"
        : "+f"(c[0]), "+f"(c[1]), "+f"(c[2]), "+f"(c[3])
        : "r"(a[0]), "r"(a[1]), "r"(a[2]), "r"(a[3]), "r"(b0), "r"(b1));
}
__device__ __forceinline__ void ldsm_x4(uint32_t* r, uint32_t addr) {
    asm volatile("ldmatrix.sync.aligned.m8n8.x4.shared.b16 {%0,%1,%2,%3}, [%4];"
                 : "=r"(r[0]), "=r"(r[1]), "=r"(r[2]), "=r"(r[3]) : "r"(addr));
}
__device__ __forceinline__ void ldsm_x2(uint32_t* r, uint32_t addr) {
    asm volatile("ldmatrix.sync.aligned.m8n8.x2.shared.b16 {%0,%1}, [%2];"
                 : "=r"(r[0]), "=r"(r[1]) : "r"(addr));
}

// ===========================================================================
// Split-bf16 GEMM + bias via mma.sync + ldmatrix; fp16 output.
// C[M,BN] = A[M,K] @ W[K,BN] + b, fp32-accurate (hi*hi + hi*lo + lo*hi).
// CTA: 128 x BN, BK=64 chunks. 8 warps 4(m) x 2(n); warp tile 32 x BN/2.
// PREFETCH: stage next A chunk in registers across the MMA loop.
// ===========================================================================
template <int K_TOTAL, int BN, bool PREFETCH>
__global__ __launch_bounds__(256) void mma_gemm_bias(
    const float* __restrict__ A, const float* __restrict__ W,
    const float* __restrict__ bias, __half* __restrict__ C, int M)
{
    constexpr int BM = 128, BK = 64, LDSW = 72;
    constexpr int CHUNKS = K_TOTAL / BK;
    constexpr int WN = BN / 2;
    constexpr int NT = WN / 8;
    constexpr int MT = 2;

    extern __shared__ __nv_bfloat16 sm[];
    __nv_bfloat16* Ah = sm;                      // [BM][LDSW]
    __nv_bfloat16* Al = sm + BM * LDSW;
    __nv_bfloat16* Bh = sm + 2 * BM * LDSW;      // [BN][LDSW]  (Bs[n][k])
    __nv_bfloat16* Bl = Bh + BN * LDSW;

    const int tid = threadIdx.x;
    const int wid = tid >> 5;
    const int lane = tid & 31;
    const int wm = wid >> 1;
    const int wn = wid & 1;
    const int lr = lane >> 2;
    const int lc = lane & 3;
    const int r0 = blockIdx.x * BM;

    const int m4    = lane >> 3;
    const int arow  = (lane & 7) + (m4 & 1) * 8;
    const int akoff = (m4 >> 1) * 8;
    const int brow  = lane & 7;
    const int bkoff = ((lane >> 3) & 1) * 8;

    const uint32_t AhB = (uint32_t)__cvta_generic_to_shared(Ah) +
                         ((wm * 32 + arow) * LDSW + akoff) * 2;
    const uint32_t AlB = (uint32_t)__cvta_generic_to_shared(Al) +
                         ((wm * 32 + arow) * LDSW + akoff) * 2;
    const uint32_t BhB = (uint32_t)__cvta_generic_to_shared(Bh) +
                         ((wn * WN + brow) * LDSW + bkoff) * 2;
    const uint32_t BlB = (uint32_t)__cvta_generic_to_shared(Bl) +
                         ((wn * WN + brow) * LDSW + bkoff) * 2;

    float acc[MT][NT][4];
#pragma unroll
    for (int i = 0; i < MT; ++i)
#pragma unroll
        for (int j = 0; j < NT; ++j)
#pragma unroll
            for (int q = 0; q < 4; ++q) acc[i][j][q] = 0.f;

    float4 aStage[8];
    auto load_stage = [&](int kc) {
#pragma unroll
        for (int it = 0; it < 8; ++it) {
            int idx = tid + it * 256;
            int row = idx >> 4;
            int j4 = (idx & 15) * 4;
            aStage[it] = make_float4(0.f, 0.f, 0.f, 0.f);
            if (r0 + row < M)
                aStage[it] = *(const float4*)(A + (size_t)(r0 + row) * K_TOTAL +
                                              kc * BK + j4);
        }
    };
    if (PREFETCH) load_stage(0);

    for (int kc = 0; kc < CHUNKS; ++kc) {
        // ---- convert + store A chunk (from stage or direct) ----
#pragma unroll
        for (int it = 0; it < 8; ++it) {
            int idx = tid + it * 256;
            int row = idx >> 4;
            int j4 = (idx & 15) * 4;
            float4 v;
            if (PREFETCH) {
                v = aStage[it];
            } else {
                v = make_float4(0.f, 0.f, 0.f, 0.f);
                if (r0 + row < M)
                    v = *(const float4*)(A + (size_t)(r0 + row) * K_TOTAL +
                                         kc * BK + j4);
            }
            __nv_bfloat162 h01 = __floats2bfloat162_rn(v.x, v.y);
            __nv_bfloat162 h23 = __floats2bfloat162_rn(v.z, v.w);
            __nv_bfloat162 l01 = __floats2bfloat162_rn(
                v.x - __bfloat162float(h01.x), v.y - __bfloat162float(h01.y));
            __nv_bfloat162 l23 = __floats2bfloat162_rn(
                v.z - __bfloat162float(h23.x), v.w - __bfloat162float(h23.y));
            int o = row * LDSW + j4;
            *(__nv_bfloat162*)(Ah + o)     = h01;
            *(__nv_bfloat162*)(Ah + o + 2) = h23;
            *(__nv_bfloat162*)(Al + o)     = l01;
            *(__nv_bfloat162*)(Al + o + 2) = l23;
        }
        // ---- load + transpose + split W chunk ----
#pragma unroll
        for (int it = 0; it < (BK * BN) / 256; ++it) {
            int idx = tid + it * 256;
            int kl = idx / BN;
            int n  = idx % BN;
            float w = __ldg(W + (size_t)(kc * BK + kl) * BN + n);
            __nv_bfloat16 hi = __float2bfloat16(w);
            __nv_bfloat16 lo = __float2bfloat16(w - __bfloat162float(hi));
            Bh[n * LDSW + kl] = hi;
            Bl[n * LDSW + kl] = lo;
        }
        __syncthreads();

        // overlap next A-chunk global loads with this chunk's MMAs
        if (PREFETCH && kc + 1 < CHUNKS) load_stage(kc + 1);

        // ---- MMA inner loop: 4 k16 steps per chunk ----
#pragma unroll
        for (int ks = 0; ks < BK / 16; ++ks) {
            const int k0 = ks * 16;
            uint32_t ah[MT][4], al[MT][4];
#pragma unroll
            for (int i = 0; i < MT; ++i) {
                ldsm_x4(ah[i], AhB + (i * 16 * LDSW + k0) * 2);
                ldsm_x4(al[i], AlB + (i * 16 * LDSW + k0) * 2);
            }
#pragma unroll
            for (int j = 0; j < NT; ++j) {
                uint32_t bh[2], bl[2];
                ldsm_x2(bh, BhB + (j * 8 * LDSW + k0) * 2);
                ldsm_x2(bl, BlB + (j * 8 * LDSW + k0) * 2);
#pragma unroll
                for (int i = 0; i < MT; ++i) {
                    mma_bf16(acc[i][j], ah[i], bh[0], bh[1]);   // hi*hi
                    mma_bf16(acc[i][j], ah[i], bl[0], bl[1]);   // hi*lo
                    mma_bf16(acc[i][j], al[i], bh[0], bh[1]);   // lo*hi
                }
            }
        }
        if (kc + 1 < CHUNKS) __syncthreads();   // protect smem reuse
    }

    // ---- epilogue: bias add + fp16 store ----
#pragma unroll
    for (int j = 0; j < NT; ++j) {
        int col = wn * WN + j * 8 + 2 * lc;
        float bb0 = __ldg(bias + col);
        float bb1 = __ldg(bias + col + 1);
#pragma unroll
        for (int i = 0; i < MT; ++i) {
            int row = r0 + wm * 32 + i * 16 + lr;
            if (row < M)
                *(__half2*)(C + (size_t)row * BN + col) =
                    __floats2half2_rn(acc[i][j][0] + bb0, acc[i][j][1] + bb1);
            if (row + 8 < M)
                *(__half2*)(C + (size_t)(row + 8) * BN + col) =
                    __floats2half2_rn(acc[i][j][2] + bb0, acc[i][j][3] + bb1);
        }
    }
}

// ===========================================================================
// CSR SpMM over fp16 features: out[r,f] = sum_e vals[e]*dense16[cols[e],f]
// Thread owns 8 features (one LDG.128 per edge). fp32 accumulate, fp32 out.
// 8-way edge unroll for gather MLP.
// ===========================================================================
template <int F, bool RELU>
__global__ __launch_bounds__(128) void spmm_fp16_kernel(
    const int* __restrict__ cols, const float* __restrict__ vals,
    const uint4* __restrict__ dense, float* __restrict__ out)
{
    constexpr int F8 = F / 8;             // threads per row
    constexpr int RPB = 128 / F8;         // rows per block
    const int r = blockIdx.x * RPB + threadIdx.x / F8;
    if (r >= N_NODES) return;
    const int f = threadIdx.x % F8;

    int e = g_rp[r];
    const int e_end = g_rp[r + 1];

    float2 a0 = make_float2(0.f, 0.f), a1 = a0, a2 = a0, a3 = a0;

    auto accum = [&](float v, uint4 d) {
        const __half2* ph = (const __half2*)&d;
        float2 x0 = __half22float2(ph[0]);
        float2 x1 = __half22float2(ph[1]);
        float2 x2 = __half22float2(ph[2]);
        float2 x3 = __half22float2(ph[3]);
        a0.x = fmaf(v, x0.x, a0.x); a0.y = fmaf(v, x0.y, a0.y);
        a1.x = fmaf(v, x1.x, a1.x); a1.y = fmaf(v, x1.y, a1.y);
        a2.x = fmaf(v, x2.x, a2.x); a2.y = fmaf(v, x2.y, a2.y);
        a3.x = fmaf(v, x3.x, a3.x); a3.y = fmaf(v, x3.y, a3.y);
    };

    for (; e + 8 <= e_end; e += 8) {
        int   c[8];
        float v[8];
#pragma unroll
        for (int u = 0; u < 8; ++u) c[u] = __ldg(cols + e + u);
#pragma unroll
        for (int u = 0; u < 8; ++u) v[u] = __ldg(vals + e + u);
        uint4 d[8];
#pragma unroll
        for (int u = 0; u < 8; ++u) d[u] = __ldg(dense + (size_t)c[u] * F8 + f);
#pragma unroll
        for (int u = 0; u < 8; ++u) accum(v[u], d[u]);
    }
    for (; e + 4 <= e_end; e += 4) {
        int   c[4];
        float v[4];
#pragma unroll
        for (int u = 0; u < 4; ++u) c[u] = __ldg(cols + e + u);
#pragma unroll
        for (int u = 0; u < 4; ++u) v[u] = __ldg(vals + e + u);
        uint4 d[4];
#pragma unroll
        for (int u = 0; u < 4; ++u) d[u] = __ldg(dense + (size_t)c[u] * F8 + f);
#pragma unroll
        for (int u = 0; u < 4; ++u) accum(v[u], d[u]);
    }
    for (; e < e_end; ++e) {
        int c = __ldg(cols + e);
        float v = __ldg(vals + e);
        accum(v, __ldg(dense + (size_t)c * F8 + f));
    }

    float4 o0 = make_float4(a0.x, a0.y, a1.x, a1.y);
    float4 o1 = make_float4(a2.x, a2.y, a3.x, a3.y);
    if (RELU) {
        o0.x = fmaxf(o0.x, 0.f); o0.y = fmaxf(o0.y, 0.f);
        o0.z = fmaxf(o0.z, 0.f); o0.w = fmaxf(o0.w, 0.f);
        o1.x = fmaxf(o1.x, 0.f); o1.y = fmaxf(o1.y, 0.f);
        o1.z = fmaxf(o1.z, 0.f); o1.w = fmaxf(o1.w, 0.f);
    }
    float* po = out + (size_t)r * F + f * 8;
    *(float4*)po       = o0;
    *(float4*)(po + 4) = o1;
}

// ===========================================================================
// Decode: out[q] = dot(z[src[q]], z[dst[q]]) over OUTF=64. Warp per edge.
// ===========================================================================
__global__ void decode_kernel(const int* __restrict__ ei,
                              const float* __restrict__ z,
                              float* __restrict__ out, int eq)
{
    int q = blockIdx.x * 8 + (threadIdx.x >> 5);
    if (q >= eq) return;
    int lane = threadIdx.x & 31;
    int s = __ldg(ei + q);
    int d = __ldg(ei + eq + q);
    const float* zs = z + (size_t)s * OUTF;
    const float* zd = z + (size_t)d * OUTF;
    float p = zs[lane] * zd[lane] + zs[lane + 32] * zd[lane + 32];
#pragma unroll
    for (int o = 16; o > 0; o >>= 1) p += __shfl_down_sync(0xffffffffu, p, o);
    if (lane == 0) out[q] = p;
}

// ===========================================================================
// Launch
// ===========================================================================
extern "C" void kernel_launch(void* const* d_in, const int* in_sizes, int n_in,
                              void* d_out, int out_size)
{
    const float* x        = (const float*)d_in[0];   // [N, 256]
    const int*   adj_rows = (const int*)  d_in[1];   // [NNZ] sorted
    const int*   adj_cols = (const int*)  d_in[2];   // [NNZ]
    const float* adj_vals = (const float*)d_in[3];   // [NNZ]
    const int*   edge_idx = (const int*)  d_in[4];   // [2, EQ]
    const float* W1       = (const float*)d_in[5];   // [256, 128]
    const float* b1       = (const float*)d_in[6];   // [128]
    const float* W2       = (const float*)d_in[7];   // [128, 64]
    const float* b2       = (const float*)d_in[8];   // [64]
    float* out = (float*)d_out;                      // [EQ]

    const int nnz = in_sizes[1];
    const int eq  = in_sizes[4] / 2;
    const int M   = N_NODES;

    uint4* h0h = nullptr; cudaGetSymbolAddress((void**)&h0h, g_h0h);
    float* h   = nullptr; cudaGetSymbolAddress((void**)&h,   g_h);
    uint4* z0h = nullptr; cudaGetSymbolAddress((void**)&z0h, g_z0h);
    float* z   = nullptr; cudaGetSymbolAddress((void**)&z,   g_z);

    // Dynamic smem: (2*BM + 2*BN) * 72 bf16 elems * 2 bytes
    constexpr int SMEM1 = (2 * 128 + 2 * 128) * 72 * 2;  // 73728 (BN=128)
    constexpr int SMEM2 = (2 * 128 + 2 * 64) * 72 * 2;   // 55296 (BN=64)
    cudaFuncSetAttribute(mma_gemm_bias<IN_F, HID, false>,
                         cudaFuncAttributeMaxDynamicSharedMemorySize, SMEM1);
    cudaFuncSetAttribute(mma_gemm_bias<HID, OUTF, true>,
                         cudaFuncAttributeMaxDynamicSharedMemorySize, SMEM2);

    const int gblocks = (M + 127) / 128;   // 782

    // 1. row pointers from sorted rows
    build_rowptr_kernel<<<(nnz + 255) / 256, 256>>>(adj_rows, nnz);

    // 2. h0 = x @ W1 + b1   (split-bf16 mma.sync, fp16 out)
    mma_gemm_bias<IN_F, HID, false><<<gblocks, 256, SMEM1>>>(
        x, W1, b1, (__half*)h0h, M);

    // 3. h = relu(spmm(h0))  (fp16 gathers, 16 thr/row, 8 rows/block)
    spmm_fp16_kernel<HID, true><<<(M + 7) / 8, 128>>>(
        adj_cols, adj_vals, h0h, h);

    // 4. z0 = h @ W2 + b2   (split-bf16 mma.sync + A prefetch, fp16 out)
    mma_gemm_bias<HID, OUTF, true><<<gblocks, 256, SMEM2>>>(
        h, W2, b2, (__half*)z0h, M);

    // 5. z = spmm(z0)        (fp16 gathers, 8 thr/row, 16 rows/block)
    spmm_fp16_kernel<OUTF, false><<<(M + 15) / 16, 128>>>(
        adj_cols, adj_vals, z0h, z);

    // 6. edge dot products
    decode_kernel<<<(eq + 7) / 8, 256>>>(edge_idx, z, out, eq);
}

// round 14
// speedup vs baseline: 2.6529x; 1.2651x over previous
#include <cuda_runtime.h>
#include <cuda_bf16.h>
#include <cuda_fp16.h>
#include <cstdint>

// Problem constants
#define N_NODES 100000
#define IN_F    256
#define HID     128
#define OUTF    64

// Scratch (device globals — no allocation allowed).
__device__ uint4 g_h0h[(size_t)N_NODES * HID / 8];   // x@W1+b1   (fp16)
__device__ float g_h [(size_t)N_NODES * HID];        // relu(spmm(h0)) fp32
__device__ uint4 g_z0h[(size_t)N_NODES * OUTF / 8];  // h@W2+b2   (fp16)
__device__ float g_z [(size_t)N_NODES * OUTF];       // spmm(z0)  fp32
__device__ int   g_rp[N_NODES + 1];                  // CSR row pointers
// Pre-split weights: bf16 hi/lo, chunk-major [kc][n][64k], 16B-aligned.
__device__ uint4 g_w1h[IN_F * HID / 8];
__device__ uint4 g_w1l[IN_F * HID / 8];
__device__ uint4 g_w2h[HID * OUTF / 8];
__device__ uint4 g_w2l[HID * OUTF / 8];

// ===========================================================================
// Build CSR row_ptr from the sorted rows array.
// ===========================================================================
__global__ void build_rowptr_kernel(const int* __restrict__ rows, int nnz) {
    int e = blockIdx.x * blockDim.x + threadIdx.x;
    if (e >= nnz) return;
    int r = rows[e];
    int rprev = (e == 0) ? -1 : rows[e - 1];
    for (int rr = rprev + 1; rr <= r; ++rr) g_rp[rr] = e;
    if (e == nnz - 1) {
        for (int rr = r + 1; rr <= N_NODES; ++rr) g_rp[rr] = nnz;
    }
}

// ===========================================================================
// Pre-split W[K,BN] fp32 -> bf16 hi/lo in chunk-major transposed layout:
//   dst[((kc*BN + n)*64 + kl)] , kc = k/64, kl = k%64
// ===========================================================================
__global__ void split_w_kernel(const float* __restrict__ W,
                               __nv_bfloat16* __restrict__ Wh,
                               __nv_bfloat16* __restrict__ Wl, int K, int BN) {
    int idx = blockIdx.x * blockDim.x + threadIdx.x;
    if (idx >= K * BN) return;
    int k = idx / BN, n = idx % BN;
    float w = W[(size_t)k * BN + n];
    __nv_bfloat16 hi = __float2bfloat16(w);
    __nv_bfloat16 lo = __float2bfloat16(w - __bfloat162float(hi));
    size_t o = ((size_t)(k >> 6) * BN + n) * 64 + (k & 63);
    Wh[o] = hi;
    Wl[o] = lo;
}

// ===========================================================================
// mma.sync m16n8k16 bf16 -> fp32 accumulate, ldmatrix, cp.async
// ===========================================================================
__device__ __forceinline__ void mma_bf16(float* c, const uint32_t* a,
                                         uint32_t b0, uint32_t b1) {
    asm volatile(
        "mma.sync.aligned.m16n8k16.row.col.f32.bf16.bf16.f32 "
        "{%0,%1,%2,%3}, {%4,%5,%6,%7}, {%8,%9}, {%0,%1,%2,%3};"
        : "+f"(c[0]), "+f"(c[1]), "+f"(c[2]), "+f"(c[3])
        : "r"(a[0]), "r"(a[1]), "r"(a[2]), "r"(a[3]), "r"(b0), "r"(b1));
}
__device__ __forceinline__ void ldsm_x4(uint32_t* r, uint32_t addr) {
    asm volatile("ldmatrix.sync.aligned.m8n8.x4.shared.b16 {%0,%1,%2,%3}, [%4];"
                 : "=r"(r[0]), "=r"(r[1]), "=r"(r[2]), "=r"(r[3]) : "r"(addr));
}
__device__ __forceinline__ void ldsm_x2(uint32_t* r, uint32_t addr) {
    asm volatile("ldmatrix.sync.aligned.m8n8.x2.shared.b16 {%0,%1}, [%2];"
                 : "=r"(r[0]), "=r"(r[1]) : "r"(addr));
}
__device__ __forceinline__ void cp_async16(uint32_t dst, const void* src) {
    size_t g = __cvta_generic_to_global(src);
    asm volatile("cp.async.cg.shared.global [%0], [%1], 16;"
                 :: "r"(dst), "l"(g) : "memory");
}
__device__ __forceinline__ void cp_commit() {
    asm volatile("cp.async.commit_group;" ::: "memory");
}
__device__ __forceinline__ void cp_wait0() {
    asm volatile("cp.async.wait_group 0;" ::: "memory");
}

// ===========================================================================
// Split-bf16 GEMM + bias, pipelined: C[M,BN] = A[M,K] @ W[K,BN] + b (fp16 out)
// fp32-accurate via hi*hi + hi*lo + lo*hi. CTA: 64 x BN, BK=64 chunks.
// 8 warps 2(m) x 4(n); warp tile 32 x BN/4.
// A chunk register-prefetched (LDG overlaps MMA); W chunk cp.async'd from
// pre-split bf16 (overlaps A convert). Smem stride 72 bf16 -> ldsm clean.
// ===========================================================================
template <int K_TOTAL, int BN>
__global__ __launch_bounds__(256) void mma_gemm_bias(
    const float* __restrict__ A,
    const __nv_bfloat16* __restrict__ Wgh, const __nv_bfloat16* __restrict__ Wgl,
    const float* __restrict__ bias, __half* __restrict__ C, int M)
{
    constexpr int BM = 64, BK = 64, LDSW = 72;
    constexpr int CHUNKS = K_TOTAL / BK;
    constexpr int WN = BN / 4;          // warp n extent (32 or 16)
    constexpr int NT = WN / 8;          // n-tiles per warp (4 or 2)
    constexpr int MT = 2;               // 32 rows per warp

    extern __shared__ __nv_bfloat16 sm[];
    __nv_bfloat16* Ah = sm;                      // [BM][LDSW]
    __nv_bfloat16* Al = sm + BM * LDSW;
    __nv_bfloat16* Bh = sm + 2 * BM * LDSW;      // [BN][LDSW]
    __nv_bfloat16* Bl = Bh + BN * LDSW;

    const int tid = threadIdx.x;
    const int wid = tid >> 5;
    const int lane = tid & 31;
    const int wm = wid >> 2;            // 0..1
    const int wn = wid & 3;             // 0..3
    const int lr = lane >> 2;
    const int lc = lane & 3;
    const int r0 = blockIdx.x * BM;

    const int m4    = lane >> 3;
    const int arow  = (lane & 7) + (m4 & 1) * 8;
    const int akoff = (m4 >> 1) * 8;
    const int brow  = lane & 7;
    const int bkoff = ((lane >> 3) & 1) * 8;

    const uint32_t smem_u32 = (uint32_t)__cvta_generic_to_shared(sm);
    const uint32_t AhB = smem_u32 + ((wm * 32 + arow) * LDSW + akoff) * 2;
    const uint32_t AlB = AhB + BM * LDSW * 2;
    const uint32_t BhU = smem_u32 + 2 * BM * LDSW * 2;   // W hi tile base
    const uint32_t BlU = BhU + BN * LDSW * 2;
    const uint32_t BhB = BhU + ((wn * WN + brow) * LDSW + bkoff) * 2;
    const uint32_t BlB = BlU + ((wn * WN + brow) * LDSW + bkoff) * 2;

    float acc[MT][NT][4];
#pragma unroll
    for (int i = 0; i < MT; ++i)
#pragma unroll
        for (int j = 0; j < NT; ++j)
#pragma unroll
            for (int q = 0; q < 4; ++q) acc[i][j][q] = 0.f;

    // ---- W chunk copy via cp.async: BN rows of 128B (8 x 16B) each ----
    auto copy_w = [&](int kc) {
        const __nv_bfloat16* gh = Wgh + (size_t)kc * BN * 64;
        const __nv_bfloat16* gl = Wgl + (size_t)kc * BN * 64;
#pragma unroll
        for (int it = 0; it < (BN * 8) / 256; ++it) {
            int idx = tid + it * 256;
            int row = idx >> 3;
            int j = idx & 7;
            cp_async16(BhU + row * (LDSW * 2) + j * 16, gh + row * 64 + j * 8);
            cp_async16(BlU + row * (LDSW * 2) + j * 16, gl + row * 64 + j * 8);
        }
        cp_commit();
    };

    // ---- A chunk stage: 64 rows x 64 cols fp32, 4 float4 per thread ----
    float4 aStage[4];
    auto load_stage = [&](int kc) {
#pragma unroll
        for (int it = 0; it < 4; ++it) {
            int idx = tid + it * 256;
            int row = idx >> 4;
            int j4 = (idx & 15) * 4;
            aStage[it] = make_float4(0.f, 0.f, 0.f, 0.f);
            if (r0 + row < M)
                aStage[it] = *(const float4*)(A + (size_t)(r0 + row) * K_TOTAL +
                                              kc * BK + j4);
        }
    };

    load_stage(0);
    copy_w(0);

    for (int kc = 0; kc < CHUNKS; ++kc) {
        // ---- convert staged A chunk -> smem hi/lo ----
#pragma unroll
        for (int it = 0; it < 4; ++it) {
            int idx = tid + it * 256;
            int row = idx >> 4;
            int j4 = (idx & 15) * 4;
            float4 v = aStage[it];
            __nv_bfloat162 h01 = __floats2bfloat162_rn(v.x, v.y);
            __nv_bfloat162 h23 = __floats2bfloat162_rn(v.z, v.w);
            __nv_bfloat162 l01 = __floats2bfloat162_rn(
                v.x - __bfloat162float(h01.x), v.y - __bfloat162float(h01.y));
            __nv_bfloat162 l23 = __floats2bfloat162_rn(
                v.z - __bfloat162float(h23.x), v.w - __bfloat162float(h23.y));
            int o = row * LDSW + j4;
            *(__nv_bfloat162*)(Ah + o)     = h01;
            *(__nv_bfloat162*)(Ah + o + 2) = h23;
            *(__nv_bfloat162*)(Al + o)     = l01;
            *(__nv_bfloat162*)(Al + o + 2) = l23;
        }
        // prefetch next A chunk (overlaps wait + MMA below)
        if (kc + 1 < CHUNKS) load_stage(kc + 1);

        cp_wait0();            // W chunk landed
        __syncthreads();

        // ---- MMA: 4 k16 steps ----
#pragma unroll
        for (int ks = 0; ks < BK / 16; ++ks) {
            const int k0 = ks * 16;
            uint32_t ah[MT][4], al[MT][4];
#pragma unroll
            for (int i = 0; i < MT; ++i) {
                ldsm_x4(ah[i], AhB + (i * 16 * LDSW + k0) * 2);
                ldsm_x4(al[i], AlB + (i * 16 * LDSW + k0) * 2);
            }
#pragma unroll
            for (int j = 0; j < NT; ++j) {
                uint32_t bh[2], bl[2];
                ldsm_x2(bh, BhB + (j * 8 * LDSW + k0) * 2);
                ldsm_x2(bl, BlB + (j * 8 * LDSW + k0) * 2);
#pragma unroll
                for (int i = 0; i < MT; ++i) {
                    mma_bf16(acc[i][j], ah[i], bh[0], bh[1]);   // hi*hi
                    mma_bf16(acc[i][j], ah[i], bl[0], bl[1]);   // hi*lo
                    mma_bf16(acc[i][j], al[i], bh[0], bh[1]);   // lo*hi
                }
            }
        }
        if (kc + 1 < CHUNKS) {
            __syncthreads();           // smem free for next chunk
            copy_w(kc + 1);            // async W fill overlaps next A convert
        }
    }

    // ---- epilogue: bias add + fp16 store ----
#pragma unroll
    for (int j = 0; j < NT; ++j) {
        int col = wn * WN + j * 8 + 2 * lc;
        float bb0 = __ldg(bias + col);
        float bb1 = __ldg(bias + col + 1);
#pragma unroll
        for (int i = 0; i < MT; ++i) {
            int row = r0 + wm * 32 + i * 16 + lr;
            if (row < M)
                *(__half2*)(C + (size_t)row * BN + col) =
                    __floats2half2_rn(acc[i][j][0] + bb0, acc[i][j][1] + bb1);
            if (row + 8 < M)
                *(__half2*)(C + (size_t)(row + 8) * BN + col) =
                    __floats2half2_rn(acc[i][j][2] + bb0, acc[i][j][3] + bb1);
        }
    }
}

// ===========================================================================
// CSR SpMM over fp16 features: out[r,f] = sum_e vals[e]*dense16[cols[e],f]
// Thread owns 8 features (one LDG.128 per edge). 8-way edge unroll.
// ===========================================================================
template <int F, bool RELU>
__global__ __launch_bounds__(128) void spmm_fp16_kernel(
    const int* __restrict__ cols, const float* __restrict__ vals,
    const uint4* __restrict__ dense, float* __restrict__ out)
{
    constexpr int F8 = F / 8;
    constexpr int RPB = 128 / F8;
    const int r = blockIdx.x * RPB + threadIdx.x / F8;
    if (r >= N_NODES) return;
    const int f = threadIdx.x % F8;

    int e = g_rp[r];
    const int e_end = g_rp[r + 1];

    float2 a0 = make_float2(0.f, 0.f), a1 = a0, a2 = a0, a3 = a0;

    auto accum = [&](float v, uint4 d) {
        const __half2* ph = (const __half2*)&d;
        float2 x0 = __half22float2(ph[0]);
        float2 x1 = __half22float2(ph[1]);
        float2 x2 = __half22float2(ph[2]);
        float2 x3 = __half22float2(ph[3]);
        a0.x = fmaf(v, x0.x, a0.x); a0.y = fmaf(v, x0.y, a0.y);
        a1.x = fmaf(v, x1.x, a1.x); a1.y = fmaf(v, x1.y, a1.y);
        a2.x = fmaf(v, x2.x, a2.x); a2.y = fmaf(v, x2.y, a2.y);
        a3.x = fmaf(v, x3.x, a3.x); a3.y = fmaf(v, x3.y, a3.y);
    };

    for (; e + 8 <= e_end; e += 8) {
        int   c[8];
        float v[8];
#pragma unroll
        for (int u = 0; u < 8; ++u) c[u] = __ldg(cols + e + u);
#pragma unroll
        for (int u = 0; u < 8; ++u) v[u] = __ldg(vals + e + u);
        uint4 d[8];
#pragma unroll
        for (int u = 0; u < 8; ++u) d[u] = __ldg(dense + (size_t)c[u] * F8 + f);
#pragma unroll
        for (int u = 0; u < 8; ++u) accum(v[u], d[u]);
    }
    for (; e + 4 <= e_end; e += 4) {
        int   c[4];
        float v[4];
#pragma unroll
        for (int u = 0; u < 4; ++u) c[u] = __ldg(cols + e + u);
#pragma unroll
        for (int u = 0; u < 4; ++u) v[u] = __ldg(vals + e + u);
        uint4 d[4];
#pragma unroll
        for (int u = 0; u < 4; ++u) d[u] = __ldg(dense + (size_t)c[u] * F8 + f);
#pragma unroll
        for (int u = 0; u < 4; ++u) accum(v[u], d[u]);
    }
    for (; e < e_end; ++e) {
        int c = __ldg(cols + e);
        float v = __ldg(vals + e);
        accum(v, __ldg(dense + (size_t)c * F8 + f));
    }

    float4 o0 = make_float4(a0.x, a0.y, a1.x, a1.y);
    float4 o1 = make_float4(a2.x, a2.y, a3.x, a3.y);
    if (RELU) {
        o0.x = fmaxf(o0.x, 0.f); o0.y = fmaxf(o0.y, 0.f);
        o0.z = fmaxf(o0.z, 0.f); o0.w = fmaxf(o0.w, 0.f);
        o1.x = fmaxf(o1.x, 0.f); o1.y = fmaxf(o1.y, 0.f);
        o1.z = fmaxf(o1.z, 0.f); o1.w = fmaxf(o1.w, 0.f);
    }
    float* po = out + (size_t)r * F + f * 8;
    *(float4*)po       = o0;
    *(float4*)(po + 4) = o1;
}

// ===========================================================================
// Decode: out[q] = dot(z[src[q]], z[dst[q]]) over OUTF=64. Warp per edge.
// ===========================================================================
__global__ void decode_kernel(const int* __restrict__ ei,
                              const float* __restrict__ z,
                              float* __restrict__ out, int eq)
{
    int q = blockIdx.x * 8 + (threadIdx.x >> 5);
    if (q >= eq) return;
    int lane = threadIdx.x & 31;
    int s = __ldg(ei + q);
    int d = __ldg(ei + eq + q);
    const float* zs = z + (size_t)s * OUTF;
    const float* zd = z + (size_t)d * OUTF;
    float p = zs[lane] * zd[lane] + zs[lane + 32] * zd[lane + 32];
#pragma unroll
    for (int o = 16; o > 0; o >>= 1) p += __shfl_down_sync(0xffffffffu, p, o);
    if (lane == 0) out[q] = p;
}

// ===========================================================================
// Launch
// ===========================================================================
extern "C" void kernel_launch(void* const* d_in, const int* in_sizes, int n_in,
                              void* d_out, int out_size)
{
    const float* x        = (const float*)d_in[0];   // [N, 256]
    const int*   adj_rows = (const int*)  d_in[1];   // [NNZ] sorted
    const int*   adj_cols = (const int*)  d_in[2];   // [NNZ]
    const float* adj_vals = (const float*)d_in[3];   // [NNZ]
    const int*   edge_idx = (const int*)  d_in[4];   // [2, EQ]
    const float* W1       = (const float*)d_in[5];   // [256, 128]
    const float* b1       = (const float*)d_in[6];   // [128]
    const float* W2       = (const float*)d_in[7];   // [128, 64]
    const float* b2       = (const float*)d_in[8];   // [64]
    float* out = (float*)d_out;                      // [EQ]

    const int nnz = in_sizes[1];
    const int eq  = in_sizes[4] / 2;
    const int M   = N_NODES;

    uint4* h0h = nullptr; cudaGetSymbolAddress((void**)&h0h, g_h0h);
    float* h   = nullptr; cudaGetSymbolAddress((void**)&h,   g_h);
    uint4* z0h = nullptr; cudaGetSymbolAddress((void**)&z0h, g_z0h);
    float* z   = nullptr; cudaGetSymbolAddress((void**)&z,   g_z);
    __nv_bfloat16* w1h = nullptr; cudaGetSymbolAddress((void**)&w1h, g_w1h);
    __nv_bfloat16* w1l = nullptr; cudaGetSymbolAddress((void**)&w1l, g_w1l);
    __nv_bfloat16* w2h = nullptr; cudaGetSymbolAddress((void**)&w2h, g_w2h);
    __nv_bfloat16* w2l = nullptr; cudaGetSymbolAddress((void**)&w2l, g_w2l);

    // Dynamic smem: (2*BM + 2*BN) * 72 elems * 2 B, BM=64
    constexpr int SMEM1 = (2 * 64 + 2 * 128) * 72 * 2;  // 55296 (BN=128)
    constexpr int SMEM2 = (2 * 64 + 2 * 64) * 72 * 2;   // 36864 (BN=64)
    cudaFuncSetAttribute(mma_gemm_bias<IN_F, HID>,
                         cudaFuncAttributeMaxDynamicSharedMemorySize, SMEM1);
    cudaFuncSetAttribute(mma_gemm_bias<HID, OUTF>,
                         cudaFuncAttributeMaxDynamicSharedMemorySize, SMEM2);

    const int gblocks = (M + 63) / 64;   // 1563

    // 0. pre-split weights (bf16 hi/lo, chunk-major transposed)
    split_w_kernel<<<(IN_F * HID + 255) / 256, 256>>>(W1, w1h, w1l, IN_F, HID);
    split_w_kernel<<<(HID * OUTF + 255) / 256, 256>>>(W2, w2h, w2l, HID, OUTF);

    // 1. row pointers from sorted rows
    build_rowptr_kernel<<<(nnz + 255) / 256, 256>>>(adj_rows, nnz);

    // 2. h0 = x @ W1 + b1
    mma_gemm_bias<IN_F, HID><<<gblocks, 256, SMEM1>>>(
        x, w1h, w1l, b1, (__half*)h0h, M);

    // 3. h = relu(spmm(h0))
    spmm_fp16_kernel<HID, true><<<(M + 7) / 8, 128>>>(
        adj_cols, adj_vals, h0h, h);

    // 4. z0 = h @ W2 + b2
    mma_gemm_bias<HID, OUTF><<<gblocks, 256, SMEM2>>>(
        h, w2h, w2l, b2, (__half*)z0h, M);

    // 5. z = spmm(z0)
    spmm_fp16_kernel<OUTF, false><<<(M + 15) / 16, 128>>>(
        adj_cols, adj_vals, z0h, z);

    // 6. edge dot products
    decode_kernel<<<(eq + 7) / 8, 256>>>(edge_idx, z, out, eq);
}